// round 15
// baseline (speedup 1.0000x reference)
#include <cuda_runtime.h>

// NaturalCubicSplinePotential — GB300 sm_103a
//
// R14: shorten the gather critical path. The int pair (IADD bits-MAGIC_I,
// IMAD *128+base) folds into ONE IMAD with a pre-biased smem base:
//   addr = bits(tm)*128 + (base - MAGIC_I*128 mod 2^32)
// (u32 wrap cancels exactly; MAGIC_I*128 ≡ 0xA0000000). Issued via PTX
// ld.shared.v4 on the folded u32 address. Also unroll 4 -> 8 (midpoint
// between R10-good-4 and R12-bad-32; body ~1.4KB fits L0 I$).
//
// Verified-kept (R13 WIN base): balanced partition, grid 888 = 148x6 exact
// single wave = 8 marginals x 111 equal ranges; conflict-free float4/NSLOT=8
// slotted gather (L1 floor ~16us measured); TABN=224 (PADL=48, |x|<=7);
// closed-form [1,4,1] inverse (31-tap conv); magic floor + midpoint
// recentering; fused deterministic last-block reduction.

#define NM 8
#define NN 128
#define TABN 224
#define PADL 48
#define NSLOT 8
#define EVAL_BLOCKS 888
#define BLOCKS_PER_M 111
#define F4_PER_M 524288            // float4 per marginal (32 slabs x 16384)
#define NTHREADS 256
#define CONV_R 15

__device__ float g_part[EVAL_BLOCKS];
__device__ unsigned int g_ticket;   // zero-init; self-resets each call

#define LOG2_LAM 1.89996863f        // log2(2+sqrt(3))
#define INV_D0   1.07735027f        // 1/(1-lam^-2)
#define MAGIC    12582912.0f        // 1.5 * 2^23
// (MAGIC_I * 128) mod 2^32 = 0xA0000000 ; bias = -that = 0x60000000
#define ADDR_BIAS 0x60000000u

// ---------------------------------------------------------------------------
__device__ __forceinline__ void eval_lane(float xv, unsigned tbase, float& acc)
{
    // t = (x+4)*15.875 + 48 (pad), midpoint-shifted: t5 = x*15.875 + 111.0
    const float t5 = __fmaf_rn(xv, 15.875f, 111.0f);
    const float tm = t5 + MAGIC;                    // round(t5) == floor(t) a.e.
    const unsigned addr = __float_as_uint(tm) * 128u + tbase;  // one IMAD
    const float v = t5 - (tm - MAGIC);              // v = u - 0.5 in [-0.5,0.5)
    float cx, cy, cz, cw;
    asm("ld.shared.v4.f32 {%0,%1,%2,%3}, [%4];"
        : "=f"(cx), "=f"(cy), "=f"(cz), "=f"(cw) : "r"(addr));
    acc += __fmaf_rn(v, __fmaf_rn(v, __fmaf_rn(v, cw, cz), cy), cx);
}

__global__ void __launch_bounds__(NTHREADS, 6)
eval_kernel(const float4* __restrict__ x4,
            const float* __restrict__ nodal,
            float* __restrict__ out)
{
    __shared__ float4 tab[TABN * NSLOT];                // 28 KB, lane-slotted
    __shared__ float  ysh[NN];
    __shared__ float  pw[256];                          // pw[k] = lam^{-k}
    __shared__ float  srsh[NN + 2 * (CONV_R + 1)];      // padded (-1)^j * r_j
    __shared__ float  csh[NN];
    __shared__ float  wsum[NTHREADS / 32];
    __shared__ bool   amLast;

    const int tid = threadIdx.x;
    const int b   = blockIdx.x;
    const int m   = b / BLOCKS_PER_M;                   // marginal 0..7
    const int q   = b - m * BLOCKS_PER_M;               // 0..110

    // balanced float4 range of this marginal
    const int jstart = (int)(((unsigned long long)q       * F4_PER_M) / BLOCKS_PER_M);
    const int jend   = (int)(((unsigned long long)(q + 1) * F4_PER_M) / BLOCKS_PER_M);

    // ---- prologue: closed-form spline solve --------------------------------
    if (tid < NN)
        ysh[tid] = nodal[m * NN + tid];
    pw[tid] = exp2f(-LOG2_LAM * (float)tid);
    if (tid < NN + 2 * (CONV_R + 1))
        srsh[tid] = 0.0f;
    __syncthreads();

    const float inv_h2 = (127.0f / 8.0f) * (127.0f / 8.0f);
    if (tid >= 1 && tid <= 126) {
        float r = 3.0f * (ysh[tid - 1] - 2.0f * ysh[tid] + ysh[tid + 1]) * inv_h2;
        srsh[(CONV_R + 1) + tid] = (tid & 1) ? -r : r;
    }
    __syncthreads();

    if (tid < NN) {
        const int i = tid;
        float c = 0.0f;
        if (i >= 1 && i <= 126) {
#pragma unroll
            for (int dj = -CONV_R; dj <= CONV_R; ++dj) {
                const int j  = i + dj;
                const int jc = min(max(j, 1), 126);
                const int mi = min(i, jc);
                const int mx = max(i, jc);
                const float w = pw[(dj < 0 ? -dj : dj) + 1]
                              * (1.0f - pw[2 * mi])
                              * (1.0f - pw[2 * (127 - mx)]);
                c = __fmaf_rn(w, srsh[(CONV_R + 1) + j], c);
            }
            c *= INV_D0;
            if (i & 1) c = -c;
        }
        csh[i] = c;
    }
    __syncthreads();

    // ---- padded + midpoint-recentered table, 8 slots -----------------------
    if (tid < TABN) {
        const float h  = 8.0f / 127.0f;
        const float h2 = h * h;
        const int j  = tid;
        const int it = j - PADL;
        const int k  = min(max(it, 0), 126);
        const float s = (float)(it - k) + 0.5f;     // shift incl. midpoint

        const float A  = ysh[k];
        const float c0 = csh[k];
        const float c1 = csh[k + 1];
        const float B  = (ysh[k + 1] - A) - h2 * (2.0f * c0 + c1) * (1.0f / 3.0f);
        const float C  = c0 * h2;
        const float D  = (c1 - c0) * h2 * (1.0f / 3.0f);

        const float4 cf = make_float4(A + s * (B + s * (C + s * D)),
                                      B + s * (2.0f * C + 3.0f * D * s),
                                      C + 3.0f * D * s,
                                      D);
#pragma unroll
        for (int sl = 0; sl < NSLOT; ++sl)
            tab[j * NSLOT + sl] = cf;
    }
    __syncthreads();

    // ---- main evaluation: balanced range of this marginal ------------------
    // pre-biased table base: addr = bits(tm)*128 + tbase lands on tab entry
    unsigned tabu32;
    asm("{ .reg .u64 t; cvta.to.shared.u64 t, %1; cvt.u32.u64 %0, t; }"
        : "=r"(tabu32) : "l"(tab));
    const unsigned tbase = tabu32 + (unsigned)((tid & 7) * 16) + ADDR_BIAS;
    const int base_m = m << 14;

    float a0 = 0.0f, a1 = 0.0f, a2 = 0.0f, a3 = 0.0f;
#pragma unroll 8
    for (int j = jstart + tid; j < jend; j += NTHREADS) {
        const int slab = j >> 14;
        const int off  = j & 16383;
        const float4 v = x4[((size_t)slab << 17) + base_m + off];
        eval_lane(v.x, tbase, a0);
        eval_lane(v.y, tbase, a1);
        eval_lane(v.z, tbase, a2);
        eval_lane(v.w, tbase, a3);
    }

    float s = (a0 + a1) + (a2 + a3);
#pragma unroll
    for (int o = 16; o > 0; o >>= 1)
        s += __shfl_xor_sync(0xFFFFFFFFu, s, o);

    if ((tid & 31) == 0)
        wsum[tid >> 5] = s;
    __syncthreads();

    if (tid == 0) {
        float t = 0.0f;
#pragma unroll
        for (int w = 0; w < NTHREADS / 32; ++w)
            t += wsum[w];
        g_part[b] = t;
        __threadfence();
        const unsigned int ticket = atomicAdd(&g_ticket, 1u);
        amLast = (ticket == EVAL_BLOCKS - 1);
    }
    __syncthreads();

    // ---- last block: deterministic fixed-order final reduction -------------
    if (amLast) {
        __threadfence();
        float r = 0.0f;
#pragma unroll
        for (int i = 0; i < 4; ++i) {
            const int idx = tid + i * NTHREADS;
            if (idx < EVAL_BLOCKS)
                r += g_part[idx];
        }

        __shared__ float sh[NTHREADS];
        sh[tid] = r;
        __syncthreads();
#pragma unroll
        for (int st = NTHREADS / 2; st > 0; st >>= 1) {
            if (tid < st)
                sh[tid] += sh[tid + st];
            __syncthreads();
        }
        if (tid == 0) {
            out[0] = sh[0];
            g_ticket = 0u;   // reset for next call / graph replay
        }
    }
}

// ---------------------------------------------------------------------------
extern "C" void kernel_launch(void* const* d_in, const int* in_sizes, int n_in,
                              void* d_out, int out_size)
{
    const float* x     = (const float*)d_in[0];        // (32,8,256,256) fp32
    const float* nodal = (const float*)d_in[1];        // (8,128) fp32
    float* out = (float*)d_out;

    eval_kernel<<<EVAL_BLOCKS, NTHREADS>>>((const float4*)x, nodal, out);
}

// round 16
// speedup vs baseline: 1.0638x; 1.0638x over previous
#include <cuda_runtime.h>

// NaturalCubicSplinePotential — GB300 sm_103a
//
// R15: unconfounded retest of the R14 address-fold on the R13 winner.
// Single change vs R13 (25.34us): the gather's int pair (IADD bits-MAGIC_I,
// IMAD *128+base) folds into ONE IMAD via a pre-biased smem base:
//   addr = bits(tm)*128 + (base - MAGIC_I*128 mod 2^32),  wrap cancels
// ((MAGIC_I*128) mod 2^32 = 0xA0000000, bias = 0x60000000). Loop stays
// unroll 4 — confirmed optimal from both sides (4 > 8 in R14, 4 > 32 in R12).
//
// Verified-kept (R13 WIN base): balanced partition, grid 888 = 148x6 exact
// single wave = 8 marginals x 111 equal float4 ranges; conflict-free
// float4/NSLOT=8 slotted gather (L1 floor ~16us measured); TABN=224 (PADL=48,
// covers |x|<=7); closed-form [1,4,1] inverse (31-tap conv); magic floor +
// midpoint recentering; fused deterministic last-block reduction.

#define NM 8
#define NN 128
#define TABN 224
#define PADL 48
#define NSLOT 8
#define EVAL_BLOCKS 888
#define BLOCKS_PER_M 111
#define F4_PER_M 524288            // float4 per marginal (32 slabs x 16384)
#define NTHREADS 256
#define CONV_R 15

__device__ float g_part[EVAL_BLOCKS];
__device__ unsigned int g_ticket;   // zero-init; self-resets each call

#define LOG2_LAM 1.89996863f        // log2(2+sqrt(3))
#define INV_D0   1.07735027f        // 1/(1-lam^-2)
#define MAGIC    12582912.0f        // 1.5 * 2^23
// (0x4B400000 * 128) mod 2^32 = 0xA0000000 ; bias = -that
#define ADDR_BIAS 0x60000000u

// ---------------------------------------------------------------------------
__device__ __forceinline__ void eval_lane(float xv, unsigned tbase, float& acc)
{
    // t = (x+4)*15.875 + 48 (pad), midpoint-shifted: t5 = x*15.875 + 111.0
    const float t5 = __fmaf_rn(xv, 15.875f, 111.0f);
    const float tm = t5 + MAGIC;                    // round(t5) == floor(t) a.e.
    const unsigned addr = __float_as_uint(tm) * 128u + tbase;  // one IMAD
    const float v = t5 - (tm - MAGIC);              // v = u - 0.5 in [-0.5,0.5)
    float cx, cy, cz, cw;
    asm("ld.shared.v4.f32 {%0,%1,%2,%3}, [%4];"
        : "=f"(cx), "=f"(cy), "=f"(cz), "=f"(cw) : "r"(addr));
    acc += __fmaf_rn(v, __fmaf_rn(v, __fmaf_rn(v, cw, cz), cy), cx);
}

__global__ void __launch_bounds__(NTHREADS, 6)
eval_kernel(const float4* __restrict__ x4,
            const float* __restrict__ nodal,
            float* __restrict__ out)
{
    __shared__ float4 tab[TABN * NSLOT];                // 28 KB, lane-slotted
    __shared__ float  ysh[NN];
    __shared__ float  pw[256];                          // pw[k] = lam^{-k}
    __shared__ float  srsh[NN + 2 * (CONV_R + 1)];      // padded (-1)^j * r_j
    __shared__ float  csh[NN];
    __shared__ float  wsum[NTHREADS / 32];
    __shared__ bool   amLast;

    const int tid = threadIdx.x;
    const int b   = blockIdx.x;
    const int m   = b / BLOCKS_PER_M;                   // marginal 0..7
    const int q   = b - m * BLOCKS_PER_M;               // 0..110

    // balanced float4 range of this marginal
    const int jstart = (int)(((unsigned long long)q       * F4_PER_M) / BLOCKS_PER_M);
    const int jend   = (int)(((unsigned long long)(q + 1) * F4_PER_M) / BLOCKS_PER_M);

    // ---- prologue: closed-form spline solve --------------------------------
    if (tid < NN)
        ysh[tid] = nodal[m * NN + tid];
    pw[tid] = exp2f(-LOG2_LAM * (float)tid);
    if (tid < NN + 2 * (CONV_R + 1))
        srsh[tid] = 0.0f;
    __syncthreads();

    const float inv_h2 = (127.0f / 8.0f) * (127.0f / 8.0f);
    if (tid >= 1 && tid <= 126) {
        float r = 3.0f * (ysh[tid - 1] - 2.0f * ysh[tid] + ysh[tid + 1]) * inv_h2;
        srsh[(CONV_R + 1) + tid] = (tid & 1) ? -r : r;
    }
    __syncthreads();

    if (tid < NN) {
        const int i = tid;
        float c = 0.0f;
        if (i >= 1 && i <= 126) {
#pragma unroll
            for (int dj = -CONV_R; dj <= CONV_R; ++dj) {
                const int j  = i + dj;
                const int jc = min(max(j, 1), 126);
                const int mi = min(i, jc);
                const int mx = max(i, jc);
                const float w = pw[(dj < 0 ? -dj : dj) + 1]
                              * (1.0f - pw[2 * mi])
                              * (1.0f - pw[2 * (127 - mx)]);
                c = __fmaf_rn(w, srsh[(CONV_R + 1) + j], c);
            }
            c *= INV_D0;
            if (i & 1) c = -c;
        }
        csh[i] = c;
    }
    __syncthreads();

    // ---- padded + midpoint-recentered table, 8 slots -----------------------
    if (tid < TABN) {
        const float h  = 8.0f / 127.0f;
        const float h2 = h * h;
        const int j  = tid;
        const int it = j - PADL;
        const int k  = min(max(it, 0), 126);
        const float s = (float)(it - k) + 0.5f;     // shift incl. midpoint

        const float A  = ysh[k];
        const float c0 = csh[k];
        const float c1 = csh[k + 1];
        const float B  = (ysh[k + 1] - A) - h2 * (2.0f * c0 + c1) * (1.0f / 3.0f);
        const float C  = c0 * h2;
        const float D  = (c1 - c0) * h2 * (1.0f / 3.0f);

        const float4 cf = make_float4(A + s * (B + s * (C + s * D)),
                                      B + s * (2.0f * C + 3.0f * D * s),
                                      C + 3.0f * D * s,
                                      D);
#pragma unroll
        for (int sl = 0; sl < NSLOT; ++sl)
            tab[j * NSLOT + sl] = cf;
    }
    __syncthreads();

    // ---- main evaluation: balanced range of this marginal ------------------
    unsigned tabu32;
    asm("{ .reg .u64 t; cvta.to.shared.u64 t, %1; cvt.u32.u64 %0, t; }"
        : "=r"(tabu32) : "l"(tab));
    const unsigned tbase = tabu32 + (unsigned)((tid & 7) * 16) + ADDR_BIAS;
    const int base_m = m << 14;

    float a0 = 0.0f, a1 = 0.0f, a2 = 0.0f, a3 = 0.0f;
#pragma unroll 4
    for (int j = jstart + tid; j < jend; j += NTHREADS) {
        const int slab = j >> 14;
        const int off  = j & 16383;
        const float4 v = x4[((size_t)slab << 17) + base_m + off];
        eval_lane(v.x, tbase, a0);
        eval_lane(v.y, tbase, a1);
        eval_lane(v.z, tbase, a2);
        eval_lane(v.w, tbase, a3);
    }

    float s = (a0 + a1) + (a2 + a3);
#pragma unroll
    for (int o = 16; o > 0; o >>= 1)
        s += __shfl_xor_sync(0xFFFFFFFFu, s, o);

    if ((tid & 31) == 0)
        wsum[tid >> 5] = s;
    __syncthreads();

    if (tid == 0) {
        float t = 0.0f;
#pragma unroll
        for (int w = 0; w < NTHREADS / 32; ++w)
            t += wsum[w];
        g_part[b] = t;
        __threadfence();
        const unsigned int ticket = atomicAdd(&g_ticket, 1u);
        amLast = (ticket == EVAL_BLOCKS - 1);
    }
    __syncthreads();

    // ---- last block: deterministic fixed-order final reduction -------------
    if (amLast) {
        __threadfence();
        float r = 0.0f;
#pragma unroll
        for (int i = 0; i < 4; ++i) {
            const int idx = tid + i * NTHREADS;
            if (idx < EVAL_BLOCKS)
                r += g_part[idx];
        }

        __shared__ float sh[NTHREADS];
        sh[tid] = r;
        __syncthreads();
#pragma unroll
        for (int st = NTHREADS / 2; st > 0; st >>= 1) {
            if (tid < st)
                sh[tid] += sh[tid + st];
            __syncthreads();
        }
        if (tid == 0) {
            out[0] = sh[0];
            g_ticket = 0u;   // reset for next call / graph replay
        }
    }
}

// ---------------------------------------------------------------------------
extern "C" void kernel_launch(void* const* d_in, const int* in_sizes, int n_in,
                              void* d_out, int out_size)
{
    const float* x     = (const float*)d_in[0];        // (32,8,256,256) fp32
    const float* nodal = (const float*)d_in[1];        // (8,128) fp32
    float* out = (float*)d_out;

    eval_kernel<<<EVAL_BLOCKS, NTHREADS>>>((const float4*)x, nodal, out);
}